// round 3
// baseline (speedup 1.0000x reference)
#include <cuda_runtime.h>

#define LSEQ 2048
#define NH 8
#define DKH 128
#define DVH 128
#define CIN 3072
#define TILE 16
#define NTILES (LSEQ/TILE)

// Scratch (static device globals; no allocation)
__device__ float  g_q [LSEQ*NH*DKH];
__device__ float  g_k [LSEQ*NH*DKH];
__device__ float  g_v [LSEQ*NH*DVH];
__device__ float2 g_eb[LSEQ*NH];

// ---------------------------------------------------------------------------
// Kernel 1: causal depthwise conv (K=4) + SiLU + split + l2norm(q,k) + q scale
// grid (L, 24), block 128: group g of 128 channels at time t.
// ---------------------------------------------------------------------------
__global__ void prep_kernel(const float* __restrict__ x,
                            const float* __restrict__ w,
                            const float* __restrict__ bias) {
    const int t = blockIdx.x;
    const int g = blockIdx.y;
    const int d = threadIdx.x;
    const int c = g*128 + d;

    const float4 wv = ((const float4*)w)[c];   // w[c][0..3], coalesced
    float acc = bias[c];
    float xv;
    xv = (t >= 3) ? x[(t-3)*CIN + c] : 0.f; acc = fmaf(xv, wv.x, acc);
    xv = (t >= 2) ? x[(t-2)*CIN + c] : 0.f; acc = fmaf(xv, wv.y, acc);
    xv = (t >= 1) ? x[(t-1)*CIN + c] : 0.f; acc = fmaf(xv, wv.z, acc);
    xv =           x[ t   *CIN + c];        acc = fmaf(xv, wv.w, acc);
    float val = acc / (1.f + expf(-acc));   // SiLU

    __shared__ float red[4];
    if (g < 16) {  // q or k: l2norm over this head's 128 dims
        float sq = val*val;
        #pragma unroll
        for (int off = 16; off; off >>= 1) sq += __shfl_xor_sync(0xffffffffu, sq, off);
        if ((d & 31) == 0) red[d >> 5] = sq;
        __syncthreads();
        float tot = red[0] + red[1] + red[2] + red[3];
        val *= rsqrtf(tot + 1e-6f);
    }
    if (g < 8) {
        g_q[(t*NH + g)*DKH + d] = val * 0.08838834764831845f;  // * DK^-0.5
    } else if (g < 16) {
        g_k[(t*NH + (g-8))*DKH + d] = val;
    } else {
        g_v[(t*NH + (g-16))*DVH + d] = val;
    }
}

// ---------------------------------------------------------------------------
// Kernel 2: gating  g = -exp(A_log)*softplus(a+dt_bias); eg = exp(g); beta
// ---------------------------------------------------------------------------
__global__ void gate_kernel(const float* __restrict__ a,
                            const float* __restrict__ b,
                            const float* __restrict__ A_log,
                            const float* __restrict__ dt_bias) {
    int i = blockIdx.x*blockDim.x + threadIdx.x;
    if (i >= LSEQ*NH) return;
    int h = i & 7;
    float xg = a[i] + dt_bias[h];
    float sp = (xg > 20.f) ? xg : log1pf(expf(xg));
    float gg = -expf(A_log[h]) * sp;
    float eg = expf(gg);
    float bt = 1.f / (1.f + expf(-b[i]));
    g_eb[i] = make_float2(eg, bt);
}

// ---------------------------------------------------------------------------
// Kernel 3: per-column sequential delta-rule scan.
// 1 warp per (head, v-column); lane owns 4 state floats (k-dims 4*lane..+3).
// CTA = 8 warps = 8 columns of one head; k/q/v/gates staged via cp.async
// double-buffered smem tiles.
//
// Per step, 3 independent dot reductions on s_old (k.s, q.s, q.k) run as
// interleaved SHFL butterflies -> single ~130cyc reduction latency per step:
//   f = beta * (v - e*(k.s_old));  o = e*(q.s_old) + (q.k)*f;  s = e*s + k*f
// ---------------------------------------------------------------------------
__device__ __forceinline__ unsigned smem_u32(const void* p) {
    return (unsigned)__cvta_generic_to_shared(p);
}
__device__ __forceinline__ void cp16(void* dst, const void* src) {
    asm volatile("cp.async.cg.shared.global [%0], [%1], 16;" :: "r"(smem_u32(dst)), "l"(src));
}
__device__ __forceinline__ void cp8(void* dst, const void* src) {
    asm volatile("cp.async.ca.shared.global [%0], [%1], 8;" :: "r"(smem_u32(dst)), "l"(src));
}
__device__ __forceinline__ void cp4(void* dst, const void* src) {
    asm volatile("cp.async.ca.shared.global [%0], [%1], 4;" :: "r"(smem_u32(dst)), "l"(src));
}
__device__ __forceinline__ void cp_commit() { asm volatile("cp.async.commit_group;"); }
template<int N> __device__ __forceinline__ void cp_wait() {
    asm volatile("cp.async.wait_group %0;" :: "n"(N));
}

struct __align__(16) TileBuf {
    float  k[TILE][DKH];
    float  q[TILE][DKH];
    float  v[TILE][8];
    float2 eb[TILE];
};

__device__ __forceinline__ void load_tile(TileBuf* b, int t0, int h, int cb, int tid) {
    #pragma unroll
    for (int i = 0; i < 2; i++) {
        int idx = i*256 + tid;      // 0..511
        int r   = idx >> 5;
        int d4  = idx & 31;
        cp16(&b->k[r][d4*4], g_k + ((t0 + r)*NH + h)*DKH + d4*4);
        cp16(&b->q[r][d4*4], g_q + ((t0 + r)*NH + h)*DKH + d4*4);
    }
    if (tid < TILE*8) {
        int r = tid >> 3, c = tid & 7;
        cp4(&b->v[r][c], g_v + ((t0 + r)*NH + h)*DVH + cb*8 + c);
    }
    if (tid < TILE) {
        cp8(&b->eb[tid], &g_eb[(t0 + tid)*NH + h]);
    }
}

__global__ void __launch_bounds__(256) scan_kernel(float* __restrict__ out) {
    __shared__ TileBuf sbuf[2];

    const int tid  = threadIdx.x;
    const int warp = tid >> 5;
    const int lane = tid & 31;
    const int h  = blockIdx.x >> 4;
    const int cb = blockIdx.x & 15;
    const int col = cb*8 + warp;

    load_tile(&sbuf[0], 0, h, cb, tid);
    cp_commit();

    // state: s[4*lane + {0..3}]
    float sx = 0.f, sy = 0.f, sz = 0.f, sw = 0.f;

    for (int tile = 0; tile < NTILES; tile++) {
        if (tile + 1 < NTILES) {
            load_tile(&sbuf[(tile+1)&1], (tile+1)*TILE, h, cb, tid);
            cp_commit();
            cp_wait<1>();
        } else {
            cp_wait<0>();
        }
        __syncthreads();

        TileBuf* b = &sbuf[tile & 1];
        const int t0 = tile*TILE;
        #pragma unroll
        for (int tt = 0; tt < TILE; tt++) {
            float4 k4 = *(const float4*)&b->k[tt][lane*4];
            float4 q4 = *(const float4*)&b->q[tt][lane*4];
            float2 eb = b->eb[tt];
            float  vt = b->v[tt][warp];

            // three independent partial dots on s_old
            float pk = fmaf(k4.x, sx, fmaf(k4.y, sy, fmaf(k4.z, sz, k4.w*sw)));
            float pq = fmaf(q4.x, sx, fmaf(q4.y, sy, fmaf(q4.z, sz, q4.w*sw)));
            float pz = fmaf(q4.x, k4.x, fmaf(q4.y, k4.y, fmaf(q4.z, k4.z, q4.w*k4.w)));
            // decayed state (off the reduction chain; overlaps the butterflies)
            float ex = eb.x*sx, ey = eb.x*sy, ez = eb.x*sz, ew = eb.x*sw;
            // interleaved butterflies (independent chains)
            #pragma unroll
            for (int off = 16; off; off >>= 1) {
                pk += __shfl_xor_sync(0xffffffffu, pk, off);
                pq += __shfl_xor_sync(0xffffffffu, pq, off);
                pz += __shfl_xor_sync(0xffffffffu, pz, off);
            }
            // f = beta * (v - e*(k.s_old))
            float f = eb.y * fmaf(-eb.x, pk, vt);
            // state update: s = e*s + k*f  (single fma per element after f)
            sx = fmaf(k4.x, f, ex);
            sy = fmaf(k4.y, f, ey);
            sz = fmaf(k4.z, f, ez);
            sw = fmaf(k4.w, f, ew);
            // output (off-chain)
            if (lane == 0) {
                float o = fmaf(pz, f, eb.x*pq);
                out[(t0 + tt)*(NH*DVH) + h*DVH + col] = o;
            }
        }
        __syncthreads();
    }
}

// ---------------------------------------------------------------------------
extern "C" void kernel_launch(void* const* d_in, const int* in_sizes, int n_in,
                              void* d_out, int out_size) {
    const float* x       = (const float*)d_in[0];  // mixed_qkv [L, 3072]
    const float* a       = (const float*)d_in[1];  // [L, 8]
    const float* bgate   = (const float*)d_in[2];  // [L, 8]
    const float* A_log   = (const float*)d_in[3];  // [8]
    const float* dt_bias = (const float*)d_in[4];  // [8]
    const float* w       = (const float*)d_in[5];  // conv_weight [3072, 4]
    const float* bias    = (const float*)d_in[6];  // conv_bias [3072]
    float* out = (float*)d_out;                    // [1, L, 8, 128] fp32

    prep_kernel<<<dim3(LSEQ, 24), 128>>>(x, w, bias);
    gate_kernel<<<(LSEQ*NH + 255)/256, 256>>>(a, bgate, A_log, dt_bias);
    scan_kernel<<<NH*16, 256>>>(out);
}